// round 1
// baseline (speedup 1.0000x reference)
#include <cuda_runtime.h>
#include <cstdint>
#include <cstddef>

#define N_NODES 50000
#define DIM 256
#define N_EDGES 800000
#define N_LAYERS 5

// ---------------- device scratch (allocation-free: .bss globals) ----------------
__device__ float g_bufA0[N_NODES * DIM];
__device__ float g_bufA1[N_NODES * DIM];
__device__ float g_bufP0[N_NODES * DIM];
__device__ float g_bufP1[N_NODES * DIM];
__device__ float g_aggA[N_NODES * DIM];
__device__ float g_aggP[N_NODES * DIM];
__device__ float g_cntA[N_NODES];
__device__ float g_cntP[N_NODES];

// ---------------- degree count ----------------
__global__ void count_kernel(const int* __restrict__ dst, float* __restrict__ cnt, int E) {
    int e = blockIdx.x * blockDim.x + threadIdx.x;
    if (e < E) atomicAdd(&cnt[dst[e]], 1.0f);
}

// ---------------- edge scatter: agg[dst] += x[src], vectorized atomics ----------------
__global__ void scatter_kernel(const float* __restrict__ x,
                               const int* __restrict__ src,
                               const int* __restrict__ dst,
                               float* __restrict__ agg, int E) {
    int e = blockIdx.x * (blockDim.x >> 5) + (threadIdx.x >> 5);
    if (e >= E) return;
    int lane = threadIdx.x & 31;
    int s = src[e];
    int d = dst[e];
    const float4* xs = reinterpret_cast<const float4*>(x + (size_t)s * DIM);
    float* ag = agg + (size_t)d * DIM;
#pragma unroll
    for (int i = 0; i < 2; i++) {
        float4 v = xs[lane + 32 * i];
        float* p = ag + (lane + 32 * i) * 4;
        asm volatile("red.global.add.v4.f32 [%0], {%1, %2, %3, %4};"
                     :: "l"(p), "f"(v.x), "f"(v.y), "f"(v.z), "f"(v.w)
                     : "memory");
    }
}

// ---------------- fused dual GEMM: out = (agg/cnt) @ Wl^T + x @ Wr^T + b ----------------
// A matrices: [M, 256] row-major. W matrices: [256, 256] row-major (n-major, k contiguous).
// BM=128, BN=64, BK=16. 256 threads, each computes 8x4 outputs.
__global__ __launch_bounds__(256, 2)
void gemm_kernel(const float* __restrict__ Aagg, const float* __restrict__ cnt,
                 const float* __restrict__ Aself,
                 const float* __restrict__ Wl, const float* __restrict__ Wr,
                 const float* __restrict__ bias,
                 float* __restrict__ out, int M) {
    __shared__ float As[16][128];
    __shared__ float Bs[16][68];   // 68*4=272 bytes per row, 16B aligned

    const int bm = blockIdx.y * 128;
    const int bn = blockIdx.x * 64;

    const int t = threadIdx.x;
    const int tx = t & 15;          // col group 0..15
    const int ty = t >> 4;          // row group 0..15

    // A-load mapping: each thread loads 2 float4 of one row
    const int row_l = t >> 1;           // 0..127
    const int kq0   = (t & 1) * 2;      // 0 or 2
    const int grow  = bm + row_l;

    // B-load mapping: one float4 per thread
    const int n_l  = t >> 2;            // 0..63
    const int kq_b = t & 3;             // 0..3

    float rscale = 0.0f;
    if (grow < M) rscale = 1.0f / fmaxf(cnt[grow], 1.0f);

    float acc[8][4];
#pragma unroll
    for (int i = 0; i < 8; i++)
#pragma unroll
        for (int j = 0; j < 4; j++) acc[i][j] = 0.0f;

#pragma unroll 1
    for (int m = 0; m < 2; m++) {
        const float* A = m ? Aself : Aagg;
        const float* B = m ? Wr : Wl;
        const float scale = m ? 1.0f : rscale;

#pragma unroll 1
        for (int kt = 0; kt < 16; kt++) {
            __syncthreads();
            // load A tile (scaled)
            {
                const float* ap = A + (size_t)grow * DIM + kt * 16;
#pragma unroll
                for (int q = 0; q < 2; q++) {
                    int kq = kq0 + q;
                    float4 v = make_float4(0.f, 0.f, 0.f, 0.f);
                    if (grow < M) v = *reinterpret_cast<const float4*>(ap + kq * 4);
                    As[kq * 4 + 0][row_l] = v.x * scale;
                    As[kq * 4 + 1][row_l] = v.y * scale;
                    As[kq * 4 + 2][row_l] = v.z * scale;
                    As[kq * 4 + 3][row_l] = v.w * scale;
                }
            }
            // load B tile
            {
                const float4 w = *reinterpret_cast<const float4*>(
                    B + (size_t)(bn + n_l) * DIM + kt * 16 + kq_b * 4);
                Bs[kq_b * 4 + 0][n_l] = w.x;
                Bs[kq_b * 4 + 1][n_l] = w.y;
                Bs[kq_b * 4 + 2][n_l] = w.z;
                Bs[kq_b * 4 + 3][n_l] = w.w;
            }
            __syncthreads();

#pragma unroll
            for (int k = 0; k < 16; k++) {
                float4 a0 = *reinterpret_cast<const float4*>(&As[k][ty * 4]);
                float4 a1 = *reinterpret_cast<const float4*>(&As[k][64 + ty * 4]);
                float4 b  = *reinterpret_cast<const float4*>(&Bs[k][tx * 4]);
                float ar[8] = {a0.x, a0.y, a0.z, a0.w, a1.x, a1.y, a1.z, a1.w};
                float br[4] = {b.x, b.y, b.z, b.w};
#pragma unroll
                for (int i = 0; i < 8; i++)
#pragma unroll
                    for (int j = 0; j < 4; j++)
                        acc[i][j] += ar[i] * br[j];
            }
        }
    }

    const float4 bb = *reinterpret_cast<const float4*>(bias + bn + tx * 4);
#pragma unroll
    for (int g = 0; g < 2; g++) {
#pragma unroll
        for (int i = 0; i < 4; i++) {
            int r = bm + g * 64 + ty * 4 + i;
            if (r < M) {
                float4 o;
                o.x = acc[g * 4 + i][0] + bb.x;
                o.y = acc[g * 4 + i][1] + bb.y;
                o.z = acc[g * 4 + i][2] + bb.z;
                o.w = acc[g * 4 + i][3] + bb.w;
                *reinterpret_cast<float4*>(out + (size_t)r * DIM + bn + tx * 4) = o;
            }
        }
    }
}

// ---------------- L2 normalize + ReLU (per row) ----------------
__global__ void norm_relu_kernel(float* __restrict__ x, int n) {
    int row = blockIdx.x * (blockDim.x >> 5) + (threadIdx.x >> 5);
    if (row >= n) return;
    int lane = threadIdx.x & 31;
    float4* p = reinterpret_cast<float4*>(x + (size_t)row * DIM);
    float4 v0 = p[lane];
    float4 v1 = p[lane + 32];
    float s = v0.x * v0.x + v0.y * v0.y + v0.z * v0.z + v0.w * v0.w
            + v1.x * v1.x + v1.y * v1.y + v1.z * v1.z + v1.w * v1.w;
#pragma unroll
    for (int o = 16; o; o >>= 1) s += __shfl_xor_sync(0xFFFFFFFFu, s, o);
    float inv = 1.0f / fmaxf(sqrtf(s), 1e-12f);
    v0.x = fmaxf(v0.x * inv, 0.f); v0.y = fmaxf(v0.y * inv, 0.f);
    v0.z = fmaxf(v0.z * inv, 0.f); v0.w = fmaxf(v0.w * inv, 0.f);
    v1.x = fmaxf(v1.x * inv, 0.f); v1.y = fmaxf(v1.y * inv, 0.f);
    v1.z = fmaxf(v1.z * inv, 0.f); v1.w = fmaxf(v1.w * inv, 0.f);
    p[lane] = v0;
    p[lane + 32] = v1;
}

// ---------------- host orchestration ----------------
extern "C" void kernel_launch(void* const* d_in, const int* in_sizes, int n_in,
                              void* d_out, int out_size) {
    (void)in_sizes; (void)n_in; (void)out_size;
    const float* xa_in = (const float*)d_in[0];
    const float* xp_in = (const float*)d_in[1];
    const float* Wl    = (const float*)d_in[2];
    const float* bl    = (const float*)d_in[3];
    const float* Wr    = (const float*)d_in[4];
    const int*   e_ap  = (const int*)d_in[5];   // [2,E]: row0 src author, row1 dst paper
    const int*   e_pa  = (const int*)d_in[6];   // [2,E]: row0 src paper, row1 dst author
    float* out = (float*)d_out;

    float *bufA[2], *bufP[2], *aggA, *aggP, *cntA, *cntP;
    cudaGetSymbolAddress((void**)&bufA[0], g_bufA0);
    cudaGetSymbolAddress((void**)&bufA[1], g_bufA1);
    cudaGetSymbolAddress((void**)&bufP[0], g_bufP0);
    cudaGetSymbolAddress((void**)&bufP[1], g_bufP1);
    cudaGetSymbolAddress((void**)&aggA, g_aggA);
    cudaGetSymbolAddress((void**)&aggP, g_aggP);
    cudaGetSymbolAddress((void**)&cntA, g_cntA);
    cudaGetSymbolAddress((void**)&cntP, g_cntP);

    const size_t featBytes = (size_t)N_NODES * DIM * sizeof(float);

    // degree counts: layer-invariant, compute once per launch
    cudaMemsetAsync(cntA, 0, N_NODES * sizeof(float));
    cudaMemsetAsync(cntP, 0, N_NODES * sizeof(float));
    count_kernel<<<(N_EDGES + 255) / 256, 256>>>(e_ap + N_EDGES, cntP, N_EDGES);
    count_kernel<<<(N_EDGES + 255) / 256, 256>>>(e_pa + N_EDGES, cntA, N_EDGES);

    const float* inA = xa_in;
    const float* inP = xp_in;

    dim3 gGrid(DIM / 64, (N_NODES + 127) / 128);   // (4, 391)
    int scatterBlocks = (N_EDGES + 7) / 8;         // 8 edges per 256-thread block
    int normBlocks = (N_NODES + 7) / 8;

    for (int l = 0; l < N_LAYERS; l++) {
        float* outA = (l == N_LAYERS - 1) ? out : bufA[l & 1];
        float* outP = (l == N_LAYERS - 1) ? out + (size_t)N_NODES * DIM : bufP[l & 1];

        cudaMemsetAsync(aggP, 0, featBytes);
        cudaMemsetAsync(aggA, 0, featBytes);

        // author -> paper
        scatter_kernel<<<scatterBlocks, 256>>>(inA, e_ap, e_ap + N_EDGES, aggP, N_EDGES);
        // paper -> author
        scatter_kernel<<<scatterBlocks, 256>>>(inP, e_pa, e_pa + N_EDGES, aggA, N_EDGES);

        const float* Wl_p = Wl + ((size_t)l * 2 + 0) * DIM * DIM;
        const float* Wr_p = Wr + ((size_t)l * 2 + 0) * DIM * DIM;
        const float* bl_p = bl + ((size_t)l * 2 + 0) * DIM;
        const float* Wl_a = Wl + ((size_t)l * 2 + 1) * DIM * DIM;
        const float* Wr_a = Wr + ((size_t)l * 2 + 1) * DIM * DIM;
        const float* bl_a = bl + ((size_t)l * 2 + 1) * DIM;

        gemm_kernel<<<gGrid, 256>>>(aggP, cntP, inP, Wl_p, Wr_p, bl_p, outP, N_NODES);
        gemm_kernel<<<gGrid, 256>>>(aggA, cntA, inA, Wl_a, Wr_a, bl_a, outA, N_NODES);

        if (l < N_LAYERS - 1) {
            norm_relu_kernel<<<normBlocks, 256>>>(outP, N_NODES);
            norm_relu_kernel<<<normBlocks, 256>>>(outA, N_NODES);
        }
        inA = outA;
        inP = outP;
    }
}

// round 2
// speedup vs baseline: 1.7133x; 1.7133x over previous
#include <cuda_runtime.h>
#include <cstdint>
#include <cstddef>

#define N_NODES 50000
#define DIM 256
#define N_EDGES 800000
#define N_LAYERS 5

// ---------------- device scratch (allocation-free: .bss globals) ----------------
__device__ float g_bufA0[N_NODES * DIM];
__device__ float g_bufA1[N_NODES * DIM];
__device__ float g_bufP0[N_NODES * DIM];
__device__ float g_bufP1[N_NODES * DIM];
__device__ float g_aggA[N_NODES * DIM];
__device__ float g_aggP[N_NODES * DIM];
__device__ float g_cntA[N_NODES];
__device__ float g_cntP[N_NODES];

// ---------------- degree count ----------------
__global__ void count_kernel(const int* __restrict__ dst, float* __restrict__ cnt, int E) {
    int e = blockIdx.x * blockDim.x + threadIdx.x;
    if (e < E) atomicAdd(&cnt[dst[e]], 1.0f);
}

// ---------------- edge scatter: agg[dst] += x[src], vectorized atomics ----------------
__global__ void scatter_kernel(const float* __restrict__ x,
                               const int* __restrict__ src,
                               const int* __restrict__ dst,
                               float* __restrict__ agg, int E) {
    int e = blockIdx.x * (blockDim.x >> 5) + (threadIdx.x >> 5);
    if (e >= E) return;
    int lane = threadIdx.x & 31;
    int s = src[e];
    int d = dst[e];
    const float4* xs = reinterpret_cast<const float4*>(x + (size_t)s * DIM);
    float* ag = agg + (size_t)d * DIM;
#pragma unroll
    for (int i = 0; i < 2; i++) {
        float4 v = xs[lane + 32 * i];
        float* p = ag + (lane + 32 * i) * 4;
        asm volatile("red.global.add.v4.f32 [%0], {%1, %2, %3, %4};"
                     :: "l"(p), "f"(v.x), "f"(v.y), "f"(v.z), "f"(v.w)
                     : "memory");
    }
}

// ---------------- tf32 tensor-core fused dual GEMM ----------------
// out = (agg @ Wl^T) * rscale + self @ Wr^T + b   (rscale applied to accumulators
// between the two K-phases — linear in A rows, so equivalent to mean-first).
// BM=128, BN=128, BK=16, 256 threads = 8 warps, warp tile 32(m) x 64(n).

__device__ __forceinline__ void cp_async16(void* smem, const void* gmem, bool pred) {
    uint32_t s = (uint32_t)__cvta_generic_to_shared(smem);
    int sz = pred ? 16 : 0;
    asm volatile("cp.async.cg.shared.global [%0], [%1], 16, %2;"
                 :: "r"(s), "l"(gmem), "r"(sz));
}

__device__ __forceinline__ uint32_t f2tf32(float f) {
    uint32_t r;
    asm("cvt.rna.tf32.f32 %0, %1;" : "=r"(r) : "f"(f));
    return r;
}

#define LDA 20   // 16 used + 4 pad: 20*(lane>>2)+(lane&3) mod 32 hits all banks once

__global__ __launch_bounds__(256, 2)
void gemm_tc_kernel(const float* __restrict__ Aagg, const float* __restrict__ cnt,
                    const float* __restrict__ Aself,
                    const float* __restrict__ Wl, const float* __restrict__ Wr,
                    const float* __restrict__ bias,
                    float* __restrict__ out, int M) {
    __shared__ float As[2][128][LDA];
    __shared__ float Bs[2][128][LDA];

    const int bm = blockIdx.y * 128;
    const int bn = blockIdx.x * 128;
    const int t = threadIdx.x;
    const int wid = t >> 5;
    const int lane = t & 31;
    const int wm = wid & 3;          // 0..3 -> 32-row slab
    const int wn = wid >> 2;         // 0..1 -> 64-col slab
    const int gid = lane >> 2;       // groupID 0..7
    const int tig = lane & 3;        // thread-in-group 0..3

    // per-thread mean scales (rows gid and gid+8 of each 16-row mma tile)
    float rs[2][2];
#pragma unroll
    for (int mi = 0; mi < 2; mi++) {
        int r = bm + wm * 32 + mi * 16 + gid;
        rs[mi][0] = (r < M)     ? 1.0f / fmaxf(cnt[r], 1.0f)     : 0.0f;
        rs[mi][1] = (r + 8 < M) ? 1.0f / fmaxf(cnt[r + 8], 1.0f) : 0.0f;
    }

    float acc[2][8][4];
#pragma unroll
    for (int mi = 0; mi < 2; mi++)
#pragma unroll
        for (int ni = 0; ni < 8; ni++)
#pragma unroll
            for (int j = 0; j < 4; j++) acc[mi][ni][j] = 0.0f;

    // ---- async tile loader: kt 0..31; phase 0 = (Aagg, Wl), phase 1 = (Aself, Wr)
    auto load_tile = [&](int stage, int kt) {
        const int phase = kt >> 4;
        const int kloc = (kt & 15) << 4;
        const float* Ap = phase ? Aself : Aagg;
        const float* Bp = phase ? Wr : Wl;
#pragma unroll
        for (int i = 0; i < 2; i++) {
            int c = t + i * 256;       // 0..511
            int row = c >> 2;
            int seg = c & 3;
            int gr = bm + row;
            cp_async16(&As[stage][row][seg * 4],
                       Ap + (size_t)gr * DIM + kloc + seg * 4, gr < M);
            cp_async16(&Bs[stage][row][seg * 4],
                       Bp + (size_t)(bn + row) * DIM + kloc + seg * 4, true);
        }
        asm volatile("cp.async.commit_group;" ::: "memory");
    };

    load_tile(0, 0);

#pragma unroll 1
    for (int kt = 0; kt < 32; kt++) {
        const int s = kt & 1;
        if (kt + 1 < 32) {
            load_tile(1 - s, kt + 1);
            asm volatile("cp.async.wait_group 1;" ::: "memory");
        } else {
            asm volatile("cp.async.wait_group 0;" ::: "memory");
        }
        __syncthreads();

#pragma unroll
        for (int kk = 0; kk < 2; kk++) {
            const int c0 = kk * 8 + tig;
            uint32_t aR[2][4];
#pragma unroll
            for (int mi = 0; mi < 2; mi++) {
                int r0 = wm * 32 + mi * 16 + gid;
                aR[mi][0] = f2tf32(As[s][r0][c0]);
                aR[mi][1] = f2tf32(As[s][r0 + 8][c0]);
                aR[mi][2] = f2tf32(As[s][r0][c0 + 4]);
                aR[mi][3] = f2tf32(As[s][r0 + 8][c0 + 4]);
            }
            uint32_t bR[8][2];
#pragma unroll
            for (int ni = 0; ni < 8; ni++) {
                int n0 = wn * 64 + ni * 8 + gid;
                bR[ni][0] = f2tf32(Bs[s][n0][c0]);
                bR[ni][1] = f2tf32(Bs[s][n0][c0 + 4]);
            }
#pragma unroll
            for (int mi = 0; mi < 2; mi++)
#pragma unroll
                for (int ni = 0; ni < 8; ni++) {
                    asm volatile(
                        "mma.sync.aligned.m16n8k8.row.col.f32.tf32.tf32.f32 "
                        "{%0,%1,%2,%3}, {%4,%5,%6,%7}, {%8,%9}, {%0,%1,%2,%3};"
                        : "+f"(acc[mi][ni][0]), "+f"(acc[mi][ni][1]),
                          "+f"(acc[mi][ni][2]), "+f"(acc[mi][ni][3])
                        : "r"(aR[mi][0]), "r"(aR[mi][1]), "r"(aR[mi][2]), "r"(aR[mi][3]),
                          "r"(bR[ni][0]), "r"(bR[ni][1]));
                }
        }

        if (kt == 15) {
            // end of neighbor-agg phase: scale partial sums by 1/deg (per row)
#pragma unroll
            for (int mi = 0; mi < 2; mi++)
#pragma unroll
                for (int ni = 0; ni < 8; ni++) {
                    acc[mi][ni][0] *= rs[mi][0];
                    acc[mi][ni][1] *= rs[mi][0];
                    acc[mi][ni][2] *= rs[mi][1];
                    acc[mi][ni][3] *= rs[mi][1];
                }
        }
        __syncthreads();
    }

    // ---- epilogue: bias add + store (float2 per fragment row)
#pragma unroll
    for (int ni = 0; ni < 8; ni++) {
        int col = bn + wn * 64 + ni * 8 + 2 * tig;
        float bx = bias[col], by = bias[col + 1];
#pragma unroll
        for (int mi = 0; mi < 2; mi++) {
            int r0 = bm + wm * 32 + mi * 16 + gid;
            if (r0 < M) {
                float2 o = make_float2(acc[mi][ni][0] + bx, acc[mi][ni][1] + by);
                *reinterpret_cast<float2*>(out + (size_t)r0 * DIM + col) = o;
            }
            if (r0 + 8 < M) {
                float2 o = make_float2(acc[mi][ni][2] + bx, acc[mi][ni][3] + by);
                *reinterpret_cast<float2*>(out + (size_t)(r0 + 8) * DIM + col) = o;
            }
        }
    }
}

// ---------------- L2 normalize + ReLU (per row) ----------------
__global__ void norm_relu_kernel(float* __restrict__ x, int n) {
    int row = blockIdx.x * (blockDim.x >> 5) + (threadIdx.x >> 5);
    if (row >= n) return;
    int lane = threadIdx.x & 31;
    float4* p = reinterpret_cast<float4*>(x + (size_t)row * DIM);
    float4 v0 = p[lane];
    float4 v1 = p[lane + 32];
    float s = v0.x * v0.x + v0.y * v0.y + v0.z * v0.z + v0.w * v0.w
            + v1.x * v1.x + v1.y * v1.y + v1.z * v1.z + v1.w * v1.w;
#pragma unroll
    for (int o = 16; o; o >>= 1) s += __shfl_xor_sync(0xFFFFFFFFu, s, o);
    float inv = 1.0f / fmaxf(sqrtf(s), 1e-12f);
    v0.x = fmaxf(v0.x * inv, 0.f); v0.y = fmaxf(v0.y * inv, 0.f);
    v0.z = fmaxf(v0.z * inv, 0.f); v0.w = fmaxf(v0.w * inv, 0.f);
    v1.x = fmaxf(v1.x * inv, 0.f); v1.y = fmaxf(v1.y * inv, 0.f);
    v1.z = fmaxf(v1.z * inv, 0.f); v1.w = fmaxf(v1.w * inv, 0.f);
    p[lane] = v0;
    p[lane + 32] = v1;
}

// ---------------- host orchestration ----------------
extern "C" void kernel_launch(void* const* d_in, const int* in_sizes, int n_in,
                              void* d_out, int out_size) {
    (void)in_sizes; (void)n_in; (void)out_size;
    const float* xa_in = (const float*)d_in[0];
    const float* xp_in = (const float*)d_in[1];
    const float* Wl    = (const float*)d_in[2];
    const float* bl    = (const float*)d_in[3];
    const float* Wr    = (const float*)d_in[4];
    const int*   e_ap  = (const int*)d_in[5];   // [2,E]: row0 src author, row1 dst paper
    const int*   e_pa  = (const int*)d_in[6];   // [2,E]: row0 src paper, row1 dst author
    float* out = (float*)d_out;

    float *bufA[2], *bufP[2], *aggA, *aggP, *cntA, *cntP;
    cudaGetSymbolAddress((void**)&bufA[0], g_bufA0);
    cudaGetSymbolAddress((void**)&bufA[1], g_bufA1);
    cudaGetSymbolAddress((void**)&bufP[0], g_bufP0);
    cudaGetSymbolAddress((void**)&bufP[1], g_bufP1);
    cudaGetSymbolAddress((void**)&aggA, g_aggA);
    cudaGetSymbolAddress((void**)&aggP, g_aggP);
    cudaGetSymbolAddress((void**)&cntA, g_cntA);
    cudaGetSymbolAddress((void**)&cntP, g_cntP);

    const size_t featBytes = (size_t)N_NODES * DIM * sizeof(float);

    // degree counts: layer-invariant, compute once per launch
    cudaMemsetAsync(cntA, 0, N_NODES * sizeof(float));
    cudaMemsetAsync(cntP, 0, N_NODES * sizeof(float));
    count_kernel<<<(N_EDGES + 255) / 256, 256>>>(e_ap + N_EDGES, cntP, N_EDGES);
    count_kernel<<<(N_EDGES + 255) / 256, 256>>>(e_pa + N_EDGES, cntA, N_EDGES);

    const float* inA = xa_in;
    const float* inP = xp_in;

    dim3 gGrid(DIM / 128, (N_NODES + 127) / 128);   // (2, 391)
    int scatterBlocks = (N_EDGES + 7) / 8;          // 8 edges per 256-thread block
    int normBlocks = (N_NODES + 7) / 8;

    for (int l = 0; l < N_LAYERS; l++) {
        float* outA = (l == N_LAYERS - 1) ? out : bufA[l & 1];
        float* outP = (l == N_LAYERS - 1) ? out + (size_t)N_NODES * DIM : bufP[l & 1];

        cudaMemsetAsync(aggP, 0, featBytes);
        cudaMemsetAsync(aggA, 0, featBytes);

        // author -> paper
        scatter_kernel<<<scatterBlocks, 256>>>(inA, e_ap, e_ap + N_EDGES, aggP, N_EDGES);
        // paper -> author
        scatter_kernel<<<scatterBlocks, 256>>>(inP, e_pa, e_pa + N_EDGES, aggA, N_EDGES);

        const float* Wl_p = Wl + ((size_t)l * 2 + 0) * DIM * DIM;
        const float* Wr_p = Wr + ((size_t)l * 2 + 0) * DIM * DIM;
        const float* bl_p = bl + ((size_t)l * 2 + 0) * DIM;
        const float* Wl_a = Wl + ((size_t)l * 2 + 1) * DIM * DIM;
        const float* Wr_a = Wr + ((size_t)l * 2 + 1) * DIM * DIM;
        const float* bl_a = bl + ((size_t)l * 2 + 1) * DIM;

        gemm_tc_kernel<<<gGrid, 256>>>(aggP, cntP, inP, Wl_p, Wr_p, bl_p, outP, N_NODES);
        gemm_tc_kernel<<<gGrid, 256>>>(aggA, cntA, inA, Wl_a, Wr_a, bl_a, outA, N_NODES);

        if (l < N_LAYERS - 1) {
            norm_relu_kernel<<<normBlocks, 256>>>(outP, N_NODES);
            norm_relu_kernel<<<normBlocks, 256>>>(outA, N_NODES);
        }
        inA = outA;
        inP = outP;
    }
}

// round 3
// speedup vs baseline: 2.6969x; 1.5740x over previous
#include <cuda_runtime.h>
#include <cstdint>
#include <cstddef>

#define N_NODES 50000
#define DIM 256
#define N_EDGES 800000
#define N_LAYERS 5

// ---------------- device scratch (allocation-free: .bss globals) ----------------
__device__ float g_bufA0[N_NODES * DIM];
__device__ float g_bufA1[N_NODES * DIM];
__device__ float g_bufP0[N_NODES * DIM];
__device__ float g_bufP1[N_NODES * DIM];
__device__ float g_aggA[N_NODES * DIM];
__device__ float g_aggP[N_NODES * DIM];
__device__ int   g_degA[N_NODES];
__device__ int   g_degP[N_NODES];
__device__ int   g_offA[N_NODES + 1];
__device__ int   g_offP[N_NODES + 1];
__device__ int   g_curA[N_NODES];
__device__ int   g_curP[N_NODES];
__device__ int   g_csrA[N_EDGES];   // paper srcs per author dst
__device__ int   g_csrP[N_EDGES];   // author srcs per paper dst

// ---------------- CSR build: degree count ----------------
__global__ void deg_kernel(const int* __restrict__ dst, int* __restrict__ deg, int E) {
    int e = blockIdx.x * blockDim.x + threadIdx.x;
    if (e < E) atomicAdd(&deg[dst[e]], 1);
}

// ---------------- CSR build: single-block exclusive scan ----------------
__global__ void scan_kernel(const int* __restrict__ deg, int* __restrict__ off, int n) {
    __shared__ int warp_sums[32];
    __shared__ int s_carry;
    const int tid = threadIdx.x;
    if (tid == 0) s_carry = 0;
    __syncthreads();
    for (int base = 0; base < n; base += 1024) {
        int i = base + tid;
        int v = (i < n) ? deg[i] : 0;
        int x = v;
#pragma unroll
        for (int o = 1; o < 32; o <<= 1) {
            int y = __shfl_up_sync(0xFFFFFFFFu, x, o);
            if ((tid & 31) >= o) x += y;
        }
        if ((tid & 31) == 31) warp_sums[tid >> 5] = x;
        __syncthreads();
        if (tid < 32) {
            int w = warp_sums[tid];
#pragma unroll
            for (int o = 1; o < 32; o <<= 1) {
                int y = __shfl_up_sync(0xFFFFFFFFu, w, o);
                if (tid >= o) w += y;
            }
            warp_sums[tid] = w;
        }
        __syncthreads();
        int incl = x + ((tid >= 32) ? warp_sums[(tid >> 5) - 1] : 0);
        int carry = s_carry;
        if (i < n) off[i] = carry + incl - v;
        __syncthreads();
        if (tid == 1023) s_carry = carry + incl;
        __syncthreads();
    }
    if (tid == 0) off[n] = s_carry;
}

// ---------------- CSR build: slot fill ----------------
__global__ void fill_kernel(const int* __restrict__ src, const int* __restrict__ dst,
                            int* __restrict__ cursor, int* __restrict__ csr, int E) {
    int e = blockIdx.x * blockDim.x + threadIdx.x;
    if (e < E) {
        int slot = atomicAdd(&cursor[dst[e]], 1);
        csr[slot] = src[e];
    }
}

// ---------------- gather: agg[dst] = mean over neighbors of x[src] ----------------
// one warp per destination row; lanes cover the 256-float row as 2 float4 each
__global__ void gather_kernel(const float* __restrict__ x, const int* __restrict__ off,
                              const int* __restrict__ csr, float* __restrict__ agg, int n) {
    int row = blockIdx.x * (blockDim.x >> 5) + (threadIdx.x >> 5);
    if (row >= n) return;
    const int lane = threadIdx.x & 31;
    const int beg = off[row], end = off[row + 1];

    float4 s0 = make_float4(0.f, 0.f, 0.f, 0.f);
    float4 s1 = make_float4(0.f, 0.f, 0.f, 0.f);
    int e = beg;
    for (; e + 1 < end; e += 2) {
        int i0 = csr[e], i1 = csr[e + 1];
        const float4* p0 = reinterpret_cast<const float4*>(x + (size_t)i0 * DIM);
        const float4* p1 = reinterpret_cast<const float4*>(x + (size_t)i1 * DIM);
        float4 a = p0[lane], b = p0[lane + 32];
        float4 c = p1[lane], d = p1[lane + 32];
        s0.x += a.x; s0.y += a.y; s0.z += a.z; s0.w += a.w;
        s1.x += b.x; s1.y += b.y; s1.z += b.z; s1.w += b.w;
        s0.x += c.x; s0.y += c.y; s0.z += c.z; s0.w += c.w;
        s1.x += d.x; s1.y += d.y; s1.z += d.z; s1.w += d.w;
    }
    if (e < end) {
        const float4* p0 = reinterpret_cast<const float4*>(x + (size_t)csr[e] * DIM);
        float4 a = p0[lane], b = p0[lane + 32];
        s0.x += a.x; s0.y += a.y; s0.z += a.z; s0.w += a.w;
        s1.x += b.x; s1.y += b.y; s1.z += b.z; s1.w += b.w;
    }
    const float inv = 1.0f / fmaxf((float)(end - beg), 1.0f);
    s0.x *= inv; s0.y *= inv; s0.z *= inv; s0.w *= inv;
    s1.x *= inv; s1.y *= inv; s1.z *= inv; s1.w *= inv;
    float4* o = reinterpret_cast<float4*>(agg + (size_t)row * DIM);
    o[lane] = s0;
    o[lane + 32] = s1;
}

// ---------------- tf32 tensor-core fused dual GEMM ----------------
// out = agg @ Wl^T + self @ Wr^T + b  (agg already holds the neighbor mean)
// BM=128, BN=128, BK=16, 256 threads = 8 warps, warp tile 32(m) x 64(n).

__device__ __forceinline__ void cp_async16(void* smem, const void* gmem, bool pred) {
    uint32_t s = (uint32_t)__cvta_generic_to_shared(smem);
    int sz = pred ? 16 : 0;
    asm volatile("cp.async.cg.shared.global [%0], [%1], 16, %2;"
                 :: "r"(s), "l"(gmem), "r"(sz));
}

__device__ __forceinline__ uint32_t f2tf32(float f) {
    uint32_t r;
    asm("cvt.rna.tf32.f32 %0, %1;" : "=r"(r) : "f"(f));
    return r;
}

#define LDA 20   // 16 used + 4 pad: conflict-free fragment loads

__global__ __launch_bounds__(256, 2)
void gemm_tc_kernel(const float* __restrict__ Aagg,
                    const float* __restrict__ Aself,
                    const float* __restrict__ Wl, const float* __restrict__ Wr,
                    const float* __restrict__ bias,
                    float* __restrict__ out, int M) {
    __shared__ float As[2][128][LDA];
    __shared__ float Bs[2][128][LDA];

    const int bm = blockIdx.y * 128;
    const int bn = blockIdx.x * 128;
    const int t = threadIdx.x;
    const int wid = t >> 5;
    const int lane = t & 31;
    const int wm = wid & 3;
    const int wn = wid >> 2;
    const int gid = lane >> 2;
    const int tig = lane & 3;

    float acc[2][8][4];
#pragma unroll
    for (int mi = 0; mi < 2; mi++)
#pragma unroll
        for (int ni = 0; ni < 8; ni++)
#pragma unroll
            for (int j = 0; j < 4; j++) acc[mi][ni][j] = 0.0f;

    auto load_tile = [&](int stage, int kt) {
        const int phase = kt >> 4;
        const int kloc = (kt & 15) << 4;
        const float* Ap = phase ? Aself : Aagg;
        const float* Bp = phase ? Wr : Wl;
#pragma unroll
        for (int i = 0; i < 2; i++) {
            int c = t + i * 256;
            int row = c >> 2;
            int seg = c & 3;
            int gr = bm + row;
            cp_async16(&As[stage][row][seg * 4],
                       Ap + (size_t)gr * DIM + kloc + seg * 4, gr < M);
            cp_async16(&Bs[stage][row][seg * 4],
                       Bp + (size_t)(bn + row) * DIM + kloc + seg * 4, true);
        }
        asm volatile("cp.async.commit_group;" ::: "memory");
    };

    load_tile(0, 0);

#pragma unroll 1
    for (int kt = 0; kt < 32; kt++) {
        const int s = kt & 1;
        if (kt + 1 < 32) {
            load_tile(1 - s, kt + 1);
            asm volatile("cp.async.wait_group 1;" ::: "memory");
        } else {
            asm volatile("cp.async.wait_group 0;" ::: "memory");
        }
        __syncthreads();

#pragma unroll
        for (int kk = 0; kk < 2; kk++) {
            const int c0 = kk * 8 + tig;
            uint32_t aR[2][4];
#pragma unroll
            for (int mi = 0; mi < 2; mi++) {
                int r0 = wm * 32 + mi * 16 + gid;
                aR[mi][0] = f2tf32(As[s][r0][c0]);
                aR[mi][1] = f2tf32(As[s][r0 + 8][c0]);
                aR[mi][2] = f2tf32(As[s][r0][c0 + 4]);
                aR[mi][3] = f2tf32(As[s][r0 + 8][c0 + 4]);
            }
            uint32_t bR[8][2];
#pragma unroll
            for (int ni = 0; ni < 8; ni++) {
                int n0 = wn * 64 + ni * 8 + gid;
                bR[ni][0] = f2tf32(Bs[s][n0][c0]);
                bR[ni][1] = f2tf32(Bs[s][n0][c0 + 4]);
            }
#pragma unroll
            for (int mi = 0; mi < 2; mi++)
#pragma unroll
                for (int ni = 0; ni < 8; ni++) {
                    asm volatile(
                        "mma.sync.aligned.m16n8k8.row.col.f32.tf32.tf32.f32 "
                        "{%0,%1,%2,%3}, {%4,%5,%6,%7}, {%8,%9}, {%0,%1,%2,%3};"
                        : "+f"(acc[mi][ni][0]), "+f"(acc[mi][ni][1]),
                          "+f"(acc[mi][ni][2]), "+f"(acc[mi][ni][3])
                        : "r"(aR[mi][0]), "r"(aR[mi][1]), "r"(aR[mi][2]), "r"(aR[mi][3]),
                          "r"(bR[ni][0]), "r"(bR[ni][1]));
                }
        }
        __syncthreads();
    }

#pragma unroll
    for (int ni = 0; ni < 8; ni++) {
        int col = bn + wn * 64 + ni * 8 + 2 * tig;
        float bx = bias[col], by = bias[col + 1];
#pragma unroll
        for (int mi = 0; mi < 2; mi++) {
            int r0 = bm + wm * 32 + mi * 16 + gid;
            if (r0 < M) {
                float2 o = make_float2(acc[mi][ni][0] + bx, acc[mi][ni][1] + by);
                *reinterpret_cast<float2*>(out + (size_t)r0 * DIM + col) = o;
            }
            if (r0 + 8 < M) {
                float2 o = make_float2(acc[mi][ni][2] + bx, acc[mi][ni][3] + by);
                *reinterpret_cast<float2*>(out + (size_t)(r0 + 8) * DIM + col) = o;
            }
        }
    }
}

// ---------------- L2 normalize + ReLU (per row) ----------------
__global__ void norm_relu_kernel(float* __restrict__ x, int n) {
    int row = blockIdx.x * (blockDim.x >> 5) + (threadIdx.x >> 5);
    if (row >= n) return;
    int lane = threadIdx.x & 31;
    float4* p = reinterpret_cast<float4*>(x + (size_t)row * DIM);
    float4 v0 = p[lane];
    float4 v1 = p[lane + 32];
    float s = v0.x * v0.x + v0.y * v0.y + v0.z * v0.z + v0.w * v0.w
            + v1.x * v1.x + v1.y * v1.y + v1.z * v1.z + v1.w * v1.w;
#pragma unroll
    for (int o = 16; o; o >>= 1) s += __shfl_xor_sync(0xFFFFFFFFu, s, o);
    float inv = 1.0f / fmaxf(sqrtf(s), 1e-12f);
    v0.x = fmaxf(v0.x * inv, 0.f); v0.y = fmaxf(v0.y * inv, 0.f);
    v0.z = fmaxf(v0.z * inv, 0.f); v0.w = fmaxf(v0.w * inv, 0.f);
    v1.x = fmaxf(v1.x * inv, 0.f); v1.y = fmaxf(v1.y * inv, 0.f);
    v1.z = fmaxf(v1.z * inv, 0.f); v1.w = fmaxf(v1.w * inv, 0.f);
    p[lane] = v0;
    p[lane + 32] = v1;
}

// ---------------- host orchestration ----------------
extern "C" void kernel_launch(void* const* d_in, const int* in_sizes, int n_in,
                              void* d_out, int out_size) {
    (void)in_sizes; (void)n_in; (void)out_size;
    const float* xa_in = (const float*)d_in[0];
    const float* xp_in = (const float*)d_in[1];
    const float* Wl    = (const float*)d_in[2];
    const float* bl    = (const float*)d_in[3];
    const float* Wr    = (const float*)d_in[4];
    const int*   e_ap  = (const int*)d_in[5];   // row0: src author, row1: dst paper
    const int*   e_pa  = (const int*)d_in[6];   // row0: src paper, row1: dst author
    float* out = (float*)d_out;

    float *bufA[2], *bufP[2], *aggA, *aggP;
    int *degA, *degP, *offA, *offP, *curA, *curP, *csrA, *csrP;
    cudaGetSymbolAddress((void**)&bufA[0], g_bufA0);
    cudaGetSymbolAddress((void**)&bufA[1], g_bufA1);
    cudaGetSymbolAddress((void**)&bufP[0], g_bufP0);
    cudaGetSymbolAddress((void**)&bufP[1], g_bufP1);
    cudaGetSymbolAddress((void**)&aggA, g_aggA);
    cudaGetSymbolAddress((void**)&aggP, g_aggP);
    cudaGetSymbolAddress((void**)&degA, g_degA);
    cudaGetSymbolAddress((void**)&degP, g_degP);
    cudaGetSymbolAddress((void**)&offA, g_offA);
    cudaGetSymbolAddress((void**)&offP, g_offP);
    cudaGetSymbolAddress((void**)&curA, g_curA);
    cudaGetSymbolAddress((void**)&curP, g_curP);
    cudaGetSymbolAddress((void**)&csrA, g_csrA);
    cudaGetSymbolAddress((void**)&csrP, g_csrP);

    // ---- CSR build (edges are layer-invariant: build once per launch) ----
    cudaMemsetAsync(degA, 0, N_NODES * sizeof(int));
    cudaMemsetAsync(degP, 0, N_NODES * sizeof(int));
    deg_kernel<<<(N_EDGES + 255) / 256, 256>>>(e_ap + N_EDGES, degP, N_EDGES);
    deg_kernel<<<(N_EDGES + 255) / 256, 256>>>(e_pa + N_EDGES, degA, N_EDGES);
    scan_kernel<<<1, 1024>>>(degP, offP, N_NODES);
    scan_kernel<<<1, 1024>>>(degA, offA, N_NODES);
    cudaMemcpyAsync(curP, offP, N_NODES * sizeof(int), cudaMemcpyDeviceToDevice);
    cudaMemcpyAsync(curA, offA, N_NODES * sizeof(int), cudaMemcpyDeviceToDevice);
    fill_kernel<<<(N_EDGES + 255) / 256, 256>>>(e_ap, e_ap + N_EDGES, curP, csrP, N_EDGES);
    fill_kernel<<<(N_EDGES + 255) / 256, 256>>>(e_pa, e_pa + N_EDGES, curA, csrA, N_EDGES);

    const float* inA = xa_in;
    const float* inP = xp_in;

    dim3 gGrid(DIM / 128, (N_NODES + 127) / 128);   // (2, 391)
    int warpBlocks = (N_NODES + 7) / 8;             // 8 warps per 256-thread block

    for (int l = 0; l < N_LAYERS; l++) {
        float* outA = (l == N_LAYERS - 1) ? out : bufA[l & 1];
        float* outP = (l == N_LAYERS - 1) ? out + (size_t)N_NODES * DIM : bufP[l & 1];

        // author -> paper mean aggregate (gather), paper -> author
        gather_kernel<<<warpBlocks, 256>>>(inA, offP, csrP, aggP, N_NODES);
        gather_kernel<<<warpBlocks, 256>>>(inP, offA, csrA, aggA, N_NODES);

        const float* Wl_p = Wl + ((size_t)l * 2 + 0) * DIM * DIM;
        const float* Wr_p = Wr + ((size_t)l * 2 + 0) * DIM * DIM;
        const float* bl_p = bl + ((size_t)l * 2 + 0) * DIM;
        const float* Wl_a = Wl + ((size_t)l * 2 + 1) * DIM * DIM;
        const float* Wr_a = Wr + ((size_t)l * 2 + 1) * DIM * DIM;
        const float* bl_a = bl + ((size_t)l * 2 + 1) * DIM;

        gemm_tc_kernel<<<gGrid, 256>>>(aggP, inP, Wl_p, Wr_p, bl_p, outP, N_NODES);
        gemm_tc_kernel<<<gGrid, 256>>>(aggA, inA, Wl_a, Wr_a, bl_a, outA, N_NODES);

        if (l < N_LAYERS - 1) {
            norm_relu_kernel<<<warpBlocks, 256>>>(outP, N_NODES);
            norm_relu_kernel<<<warpBlocks, 256>>>(outA, N_NODES);
        }
        inA = outA;
        inP = outP;
    }
}